// round 4
// baseline (speedup 1.0000x reference)
#include <cuda_runtime.h>
#include <cstdint>

#define T_DIM 8192
#define D_DIM 4096
#define E_DIM 64

// ---------------------------------------------------------------------------
// GEMM: logits[T,E] = H[T,D] @ W[E,D]^T + bias[E], pure fp32 accuracy using
// packed fma.rn.f32x2 (2 FMAs/instr; FFMA 3-reg is half-rate on sm_103a).
// Block: 256 threads, tile 64 rows x 64 experts x 32 K, per-thread 4x4 with
// f32x2 pairs over K (even/odd K accumulate in lo/hi, summed at the end).
// ---------------------------------------------------------------------------

constexpr int BM  = 64;
constexpr int BK  = 32;
constexpr int KKP = BK / 2;   // 16 k-pairs per tile

__device__ __forceinline__ unsigned long long ffma2(unsigned long long a,
                                                    unsigned long long b,
                                                    unsigned long long c) {
    unsigned long long d;
    asm("fma.rn.f32x2 %0, %1, %2, %3;" : "=l"(d) : "l"(a), "l"(b), "l"(c));
    return d;
}

__global__ __launch_bounds__(256) void gemm_kernel(
    const float* __restrict__ H, const float* __restrict__ Wm,
    const float* __restrict__ bias, float* __restrict__ logits)
{
    // [k-pair][row] layout so 4 consecutive rows load as one LDS.128.
    // Pad rows 64->66: row stride 528B stays 16B-aligned.
    __shared__ __align__(16) float2 hs[KKP][BM + 2];
    __shared__ __align__(16) float2 ws[KKP][E_DIM + 2];

    const int tid = threadIdx.x;
    const int tx  = tid & 15;   // row group: rows tx*4 .. tx*4+3
    const int ty  = tid >> 4;   // expert group: experts ty*4 .. ty*4+3
    const int row0 = blockIdx.x * BM;

    unsigned long long acc[4][4];
#pragma unroll
    for (int i = 0; i < 4; i++)
#pragma unroll
        for (int j = 0; j < 4; j++) acc[i][j] = 0ull;

    for (int k0 = 0; k0 < D_DIM; k0 += BK) {
        // Load tile: 64 rows x 8 float4 (=32 k) for both H and W. Coalesced.
#pragma unroll
        for (int hh = 0; hh < 2; hh++) {
            int q = tid + hh * 256;
            int r = q >> 3, s = q & 7;
            float4 hv = *reinterpret_cast<const float4*>(
                &H[(size_t)(row0 + r) * D_DIM + k0 + s * 4]);
            hs[s * 2    ][r] = make_float2(hv.x, hv.y);
            hs[s * 2 + 1][r] = make_float2(hv.z, hv.w);
            float4 wv = *reinterpret_cast<const float4*>(
                &Wm[(size_t)r * D_DIM + k0 + s * 4]);
            ws[s * 2    ][r] = make_float2(wv.x, wv.y);
            ws[s * 2 + 1][r] = make_float2(wv.z, wv.w);
        }
        __syncthreads();

#pragma unroll
        for (int kk = 0; kk < KKP; kk++) {
            const ulonglong2 a01 = *reinterpret_cast<const ulonglong2*>(&hs[kk][tx * 4]);
            const ulonglong2 a23 = *reinterpret_cast<const ulonglong2*>(&hs[kk][tx * 4 + 2]);
            const ulonglong2 b01 = *reinterpret_cast<const ulonglong2*>(&ws[kk][ty * 4]);
            const ulonglong2 b23 = *reinterpret_cast<const ulonglong2*>(&ws[kk][ty * 4 + 2]);
            unsigned long long a[4] = {a01.x, a01.y, a23.x, a23.y};
            unsigned long long b[4] = {b01.x, b01.y, b23.x, b23.y};
#pragma unroll
            for (int i = 0; i < 4; i++)
#pragma unroll
                for (int j = 0; j < 4; j++)
                    acc[i][j] = ffma2(a[i], b[j], acc[i][j]);
        }
        __syncthreads();
    }

#pragma unroll
    for (int i = 0; i < 4; i++) {
        int row = row0 + tx * 4 + i;
#pragma unroll
        for (int j = 0; j < 4; j++) {
            int e = ty * 4 + j;
            float2 v = *reinterpret_cast<float2*>(&acc[i][j]);
            logits[(size_t)row * E_DIM + e] = v.x + v.y + bias[e];
        }
    }
}

// ---------------------------------------------------------------------------
// Epilogue: per row -> JAX partitionable-threefry Gumbel, softmax(logits),
// rank-based top-k mask. One warp per row (2 experts per lane).
//
// Partitionable scheme, bit_width=32 (jax/_src/prng.py):
//   counts = 64-bit row-major iota over shape -> pair (hi, lo) = (0, i)
//   bits1, bits2 = threefry2x32(key, (0, i))
//   bits[i] = bits1 ^ bits2            <-- XOR of both output words
// ---------------------------------------------------------------------------

__device__ __forceinline__ uint32_t rotl32(uint32_t x, int r) {
    return (x << r) | (x >> (32 - r));
}

// x0 ^ x1 of JAX threefry2x32 with key = (0, 42), counter pair (0, i).
__device__ __forceinline__ uint32_t threefry_xor_42(uint32_t c1) {
    const uint32_t ks0 = 0u, ks1 = 42u;
    const uint32_t ks2 = 0x1BD11BDAu ^ ks0 ^ ks1;
    uint32_t x0 = 0u + ks0, x1 = c1 + ks1;
#define TF_R(r) { x0 += x1; x1 = rotl32(x1, (r)); x1 ^= x0; }
    TF_R(13) TF_R(15) TF_R(26) TF_R(6)   x0 += ks1; x1 += ks2 + 1u;
    TF_R(17) TF_R(29) TF_R(16) TF_R(24)  x0 += ks2; x1 += ks0 + 2u;
    TF_R(13) TF_R(15) TF_R(26) TF_R(6)   x0 += ks0; x1 += ks1 + 3u;
    TF_R(17) TF_R(29) TF_R(16) TF_R(24)  x0 += ks1; x1 += ks2 + 4u;
    TF_R(13) TF_R(15) TF_R(26) TF_R(6)   x0 += ks2; x1 += ks0 + 5u;
#undef TF_R
    return x0 ^ x1;
}

// Matches jax.random.uniform(minval=1e-6, maxval=1-1e-6) in f32 bit-for-bit
// (unfused mul+add as XLA emits), then g = -log(-log(u)).
__device__ __forceinline__ float gumbel_from_bits(uint32_t bits) {
    float f = __uint_as_float((bits >> 9) | 0x3F800000u) - 1.0f;
    const float lo = 1e-6f;
    const float hi = (float)(1.0 - 1e-6);     // double-rounded like Python
    float u = fmaxf(lo, __fadd_rn(__fmul_rn(f, __fsub_rn(hi, lo)), lo));
    return -logf(-logf(u));
}

__global__ __launch_bounds__(256) void epilogue_kernel(
    const float* __restrict__ logits, const int* __restrict__ kptr,
    float* __restrict__ mask_out, float* __restrict__ wout)
{
    __shared__ float ss[8][64];
    const int w    = threadIdx.x >> 5;
    const int lane = threadIdx.x & 31;
    const int row  = blockIdx.x * 8 + w;
    const int k    = *kptr;
    const int e0 = lane, e1 = lane + 32;
    const size_t base = (size_t)row * E_DIM;

    float l0 = logits[base + e0];
    float l1 = logits[base + e1];

    uint32_t i0 = (uint32_t)(row * E_DIM + e0);
    float g0 = gumbel_from_bits(threefry_xor_42(i0));
    float g1 = gumbel_from_bits(threefry_xor_42(i0 + 32u));
    float s0 = l0 + g0, s1 = l1 + g1;

    // softmax over clean logits
    float m = fmaxf(l0, l1);
#pragma unroll
    for (int off = 16; off; off >>= 1)
        m = fmaxf(m, __shfl_xor_sync(0xffffffffu, m, off));
    float p0 = expf(l0 - m), p1 = expf(l1 - m);
    float sum = p0 + p1;
#pragma unroll
    for (int off = 16; off; off >>= 1)
        sum += __shfl_xor_sync(0xffffffffu, sum, off);

    // top-k by rank (ties -> lower index wins, matching lax.top_k)
    ss[w][e0] = s0;
    ss[w][e1] = s1;
    __syncwarp();
    int c0 = 0, c1 = 0;
#pragma unroll
    for (int jj = 0; jj < 64; jj++) {
        float v = ss[w][jj];
        c0 += (v > s0) || ((v == s0) && (jj < e0));
        c1 += (v > s1) || ((v == s1) && (jj < e1));
    }

    mask_out[base + e0] = (c0 < k) ? 1.0f : 0.0f;
    mask_out[base + e1] = (c1 < k) ? 1.0f : 0.0f;
    wout[base + e0] = p0 / sum;
    wout[base + e1] = p1 / sum;
}

// ---------------------------------------------------------------------------
// Launch. Inputs identified BY ELEMENT COUNT (robust to ordering):
// h = 33,554,432 elems; W = 262,144; bias = 64; k = 1.
// out = [mask (T*E) | weight (T*E) | logits (T*E)] as float32.
// GEMM writes logits directly into its output slot; epilogue consumes it.
// ---------------------------------------------------------------------------

extern "C" void kernel_launch(void* const* d_in, const int* in_sizes, int n_in,
                              void* d_out, int out_size) {
    const float* H    = nullptr;
    const float* Wm   = nullptr;
    const float* bias = nullptr;
    const int*   kptr = nullptr;

    for (int i = 0; i < n_in; i++) {
        long long sz = in_sizes[i];
        if (sz == (long long)T_DIM * D_DIM)      H    = (const float*)d_in[i];
        else if (sz == (long long)E_DIM * D_DIM) Wm   = (const float*)d_in[i];
        else if (sz == E_DIM)                    bias = (const float*)d_in[i];
        else if (sz == 1)                        kptr = (const int*)d_in[i];
    }
    if (!H)    H    = (const float*)d_in[0];
    if (!Wm)   Wm   = (const float*)d_in[1];
    if (!bias) bias = (const float*)d_in[2];
    if (!kptr) kptr = (const int*)d_in[3];

    float* out        = (float*)d_out;
    float* mask_out   = out;
    float* weight_out = out + (size_t)T_DIM * E_DIM;
    float* logits_out = out + 2 * (size_t)T_DIM * E_DIM;

    gemm_kernel<<<T_DIM / BM, 256>>>(H, Wm, bias, logits_out);
    epilogue_kernel<<<T_DIM / 8, 256>>>(logits_out, kptr, mask_out, weight_out);
}

// round 6
// speedup vs baseline: 2.0989x; 2.0989x over previous
#include <cuda_runtime.h>
#include <cstdint>

#define T_DIM 8192
#define D_DIM 4096
#define E_DIM 64

// ===========================================================================
// GEMM: logits partials via fp32 FFMA2 (fma.rn.f32x2), conflict-free smem.
// Grid: 64 M-tiles (128 rows) x 4 K-splits (1024 K each) = 256 CTAs.
// Block: 256 threads; per-thread 4 rows x 8 experts, packed k-pair accums.
//   tx = tid&31 -> rows {tx + 32i}, i<4  (lane-consecutive LDS -> no conflicts)
//   ty = tid>>5 -> experts ty*8..ty*8+7 (warp-uniform -> LDS broadcast)
// ===========================================================================

constexpr int BM      = 128;
constexpr int BK      = 16;
constexpr int KKP     = BK / 2;          // 8 k-pairs per chunk
constexpr int KSPLIT  = 4;
constexpr int KRANGE  = D_DIM / KSPLIT;  // 1024
constexpr int NCHUNK  = KRANGE / BK;     // 64

__device__ float g_partial[KSPLIT][(size_t)T_DIM * E_DIM];   // 8 MB scratch

__device__ __forceinline__ unsigned long long ffma2(unsigned long long a,
                                                    unsigned long long b,
                                                    unsigned long long c) {
    unsigned long long d;
    asm("fma.rn.f32x2 %0, %1, %2, %3;" : "=l"(d) : "l"(a), "l"(b), "l"(c));
    return d;
}

__global__ __launch_bounds__(256, 2) void gemm_kernel(
    const float* __restrict__ H, const float* __restrict__ Wm)
{
    // hs[kk][row]: row reads are lane-consecutive (conflict-free LDS.64).
    // Pads (129 / 66) keep STS phases bank-disjoint; 66 keeps ws rows 16B-aligned.
    __shared__ __align__(16) float2 hs[KKP][BM + 1];
    __shared__ __align__(16) float2 ws[KKP][E_DIM + 2];

    const int tid = threadIdx.x;
    const int tx  = tid & 31;
    const int ty  = tid >> 5;
    const int mtile = blockIdx.x >> 2;
    const int split = blockIdx.x & 3;
    const int row0  = mtile * BM;
    const int kb0   = split * KRANGE;

    unsigned long long acc[4][8];
#pragma unroll
    for (int i = 0; i < 4; i++)
#pragma unroll
        for (int j = 0; j < 8; j++) acc[i][j] = 0ull;

    // Load indices (fixed per thread): A chunk = 128x16 fp32 = 512 float4,
    // 2 per thread; W chunk = 64x16 = 256 float4, 1 per thread.
    const int ra_r0 = tid >> 2,          ra_s0 = tid & 3;
    const int ra_r1 = (tid + 256) >> 2,  ra_s1 = tid & 3;   // q=tid+256: s unchanged
    const int rw_r  = tid >> 2,          rw_s  = tid & 3;

    float4 ra0, ra1, rwv;
    {   // prefetch chunk 0
        ra0 = *(const float4*)(H + (size_t)(row0 + ra_r0) * D_DIM + kb0 + ra_s0 * 4);
        ra1 = *(const float4*)(H + (size_t)(row0 + ra_r1) * D_DIM + kb0 + ra_s1 * 4);
        rwv = *(const float4*)(Wm + (size_t)rw_r * D_DIM + kb0 + rw_s * 4);
    }

    for (int c = 0; c < NCHUNK; c++) {
        __syncthreads();   // previous chunk's readers done
        hs[ra_s0 * 2    ][ra_r0] = make_float2(ra0.x, ra0.y);
        hs[ra_s0 * 2 + 1][ra_r0] = make_float2(ra0.z, ra0.w);
        hs[ra_s1 * 2    ][ra_r1] = make_float2(ra1.x, ra1.y);
        hs[ra_s1 * 2 + 1][ra_r1] = make_float2(ra1.z, ra1.w);
        ws[rw_s * 2     ][rw_r]  = make_float2(rwv.x, rwv.y);
        ws[rw_s * 2 + 1 ][rw_r]  = make_float2(rwv.z, rwv.w);
        __syncthreads();

        if (c + 1 < NCHUNK) {   // prefetch next chunk (overlaps compute)
            const int kb = kb0 + (c + 1) * BK;
            ra0 = *(const float4*)(H + (size_t)(row0 + ra_r0) * D_DIM + kb + ra_s0 * 4);
            ra1 = *(const float4*)(H + (size_t)(row0 + ra_r1) * D_DIM + kb + ra_s1 * 4);
            rwv = *(const float4*)(Wm + (size_t)rw_r * D_DIM + kb + rw_s * 4);
        }

#pragma unroll
        for (int kk = 0; kk < KKP; kk++) {
            const ulonglong2 b01 = *(const ulonglong2*)&ws[kk][ty * 8];
            const ulonglong2 b23 = *(const ulonglong2*)&ws[kk][ty * 8 + 2];
            const ulonglong2 b45 = *(const ulonglong2*)&ws[kk][ty * 8 + 4];
            const ulonglong2 b67 = *(const ulonglong2*)&ws[kk][ty * 8 + 6];
            const unsigned long long b[8] = {b01.x, b01.y, b23.x, b23.y,
                                             b45.x, b45.y, b67.x, b67.y};
            unsigned long long a[4];
#pragma unroll
            for (int i = 0; i < 4; i++)
                a[i] = *(const unsigned long long*)&hs[kk][tx + 32 * i];
#pragma unroll
            for (int i = 0; i < 4; i++)
#pragma unroll
                for (int j = 0; j < 8; j++)
                    acc[i][j] = ffma2(a[i], b[j], acc[i][j]);
        }
    }

    // Write partials: per row, experts ty*8..ty*8+7 as two float4 stores.
#pragma unroll
    for (int i = 0; i < 4; i++) {
        const int row = row0 + tx + 32 * i;
        float r[8];
#pragma unroll
        for (int j = 0; j < 8; j++) {
            float2 v = *reinterpret_cast<float2*>(&acc[i][j]);
            r[j] = v.x + v.y;
        }
        float* dst = &g_partial[split][(size_t)row * E_DIM + ty * 8];
        *(float4*)(dst)     = make_float4(r[0], r[1], r[2], r[3]);
        *(float4*)(dst + 4) = make_float4(r[4], r[5], r[6], r[7]);
    }
}

// ===========================================================================
// Epilogue: logits = sum of 4 K-split partials + bias; JAX partitionable
// threefry Gumbel (bits = x0^x1), softmax(clean logits), rank top-k mask.
// ===========================================================================

__device__ __forceinline__ uint32_t rotl32(uint32_t x, int r) {
    return (x << r) | (x >> (32 - r));
}
__device__ __forceinline__ uint32_t threefry_xor_42(uint32_t c1) {
    const uint32_t ks0 = 0u, ks1 = 42u;
    const uint32_t ks2 = 0x1BD11BDAu ^ ks0 ^ ks1;
    uint32_t x0 = 0u + ks0, x1 = c1 + ks1;
#define TF_R(r) { x0 += x1; x1 = rotl32(x1, (r)); x1 ^= x0; }
    TF_R(13) TF_R(15) TF_R(26) TF_R(6)   x0 += ks1; x1 += ks2 + 1u;
    TF_R(17) TF_R(29) TF_R(16) TF_R(24)  x0 += ks2; x1 += ks0 + 2u;
    TF_R(13) TF_R(15) TF_R(26) TF_R(6)   x0 += ks0; x1 += ks1 + 3u;
    TF_R(17) TF_R(29) TF_R(16) TF_R(24)  x0 += ks1; x1 += ks2 + 4u;
    TF_R(13) TF_R(15) TF_R(26) TF_R(6)   x0 += ks2; x1 += ks0 + 5u;
#undef TF_R
    return x0 ^ x1;
}
__device__ __forceinline__ float gumbel_from_bits(uint32_t bits) {
    float f = __uint_as_float((bits >> 9) | 0x3F800000u) - 1.0f;
    const float lo = 1e-6f;
    const float hi = (float)(1.0 - 1e-6);
    float u = fmaxf(lo, __fadd_rn(__fmul_rn(f, __fsub_rn(hi, lo)), lo));
    return -logf(-logf(u));
}

__global__ __launch_bounds__(256) void epilogue_kernel(
    const float* __restrict__ bias, const int* __restrict__ kptr,
    float* __restrict__ mask_out, float* __restrict__ wout,
    float* __restrict__ logits_out)
{
    __shared__ float ss[8][64];
    const int w    = threadIdx.x >> 5;
    const int lane = threadIdx.x & 31;
    const int row  = blockIdx.x * 8 + w;
    const int k    = *kptr;
    const int e0 = lane, e1 = lane + 32;
    const size_t base = (size_t)row * E_DIM;

    float l0 = ((g_partial[0][base + e0] + g_partial[1][base + e0])
              + (g_partial[2][base + e0] + g_partial[3][base + e0])) + bias[e0];
    float l1 = ((g_partial[0][base + e1] + g_partial[1][base + e1])
              + (g_partial[2][base + e1] + g_partial[3][base + e1])) + bias[e1];
    logits_out[base + e0] = l0;
    logits_out[base + e1] = l1;

    uint32_t i0 = (uint32_t)(row * E_DIM + e0);
    float s0 = l0 + gumbel_from_bits(threefry_xor_42(i0));
    float s1 = l1 + gumbel_from_bits(threefry_xor_42(i0 + 32u));

    float m = fmaxf(l0, l1);
#pragma unroll
    for (int off = 16; off; off >>= 1)
        m = fmaxf(m, __shfl_xor_sync(0xffffffffu, m, off));
    float p0 = expf(l0 - m), p1 = expf(l1 - m);
    float sum = p0 + p1;
#pragma unroll
    for (int off = 16; off; off >>= 1)
        sum += __shfl_xor_sync(0xffffffffu, sum, off);

    ss[w][e0] = s0;
    ss[w][e1] = s1;
    __syncwarp();
    int c0 = 0, c1 = 0;
#pragma unroll
    for (int jj = 0; jj < 64; jj++) {
        float v = ss[w][jj];
        c0 += (v > s0) || ((v == s0) && (jj < e0));
        c1 += (v > s1) || ((v == s1) && (jj < e1));
    }

    mask_out[base + e0] = (c0 < k) ? 1.0f : 0.0f;
    mask_out[base + e1] = (c1 < k) ? 1.0f : 0.0f;
    wout[base + e0] = p0 / sum;
    wout[base + e1] = p1 / sum;
}

// ===========================================================================
// Launch. Inputs matched by element count (h=33.5M, W=262144, bias=64, k=1).
// out = [mask | weight | logits], each T*E float32.
// ===========================================================================
extern "C" void kernel_launch(void* const* d_in, const int* in_sizes, int n_in,
                              void* d_out, int out_size) {
    const float* H    = nullptr;
    const float* Wm   = nullptr;
    const float* bias = nullptr;
    const int*   kptr = nullptr;
    for (int i = 0; i < n_in; i++) {
        long long sz = in_sizes[i];
        if (sz == (long long)T_DIM * D_DIM)      H    = (const float*)d_in[i];
        else if (sz == (long long)E_DIM * D_DIM) Wm   = (const float*)d_in[i];
        else if (sz == E_DIM)                    bias = (const float*)d_in[i];
        else if (sz == 1)                        kptr = (const int*)d_in[i];
    }
    if (!H)    H    = (const float*)d_in[0];
    if (!Wm)   Wm   = (const float*)d_in[1];
    if (!bias) bias = (const float*)d_in[2];
    if (!kptr) kptr = (const int*)d_in[3];

    float* out        = (float*)d_out;
    float* mask_out   = out;
    float* weight_out = out + (size_t)T_DIM * E_DIM;
    float* logits_out = out + 2 * (size_t)T_DIM * E_DIM;

    gemm_kernel<<<(T_DIM / BM) * KSPLIT, 256>>>(H, Wm);
    epilogue_kernel<<<T_DIM / 8, 256>>>(bias, kptr, mask_out, weight_out, logits_out);
}

// round 7
// speedup vs baseline: 2.4112x; 1.1488x over previous
#include <cuda_runtime.h>
#include <cuda_bf16.h>
#include <cstdint>

#define T_DIM 8192
#define D_DIM 4096
#define E_DIM 64

// ===========================================================================
// GEMM via legacy tensor-core mma.sync (bf16, base PTX => compiles for sm_103).
// Exact bf16x3 split: x = hi + mid + lo (each residual fits bf16 exactly).
// Products kept: hi*hi (main acc) ; hi*mid, mid*hi, mid*mid, hi*lo, lo*hi
// (correction acc). Dropped terms are O(2^-27) -> ~8e-7 rms on logits.
// Grid: 64 M-tiles (128 rows) x K-split 2 (2048 K) = 128 CTAs, 256 threads.
// Per warp: one 16-row m-tile x 64 experts; per 16-K step: 15 ldmatrix.x4
// + 48 mma.sync.m16n8k16, swept term-major so acc chains are 8 apart.
// ===========================================================================

constexpr int KSPLIT  = 2;
constexpr int KRANGE  = D_DIM / KSPLIT;   // 2048
constexpr int BKC     = 64;               // K per chunk
constexpr int NCHUNK  = KRANGE / BKC;     // 32
constexpr int PITCH   = 144;              // bytes per bf16 row (128 data + 16 pad)
constexpr int A_PLANE = 128 * PITCH;      // 18432
constexpr int B_PLANE = 64 * PITCH;       // 9216
constexpr int SB_OFF  = 3 * A_PLANE;      // 55296
constexpr int SMEM_BYTES = 3 * A_PLANE + 3 * B_PLANE;   // 82944

__device__ float g_partial[KSPLIT][(size_t)T_DIM * E_DIM];   // 4 MB scratch

__device__ __forceinline__ uint32_t smem_to_u32(const void* p) {
    uint32_t a;
    asm("{ .reg .u64 t; cvta.to.shared.u64 t, %1; cvt.u32.u64 %0, t; }"
        : "=r"(a) : "l"(p));
    return a;
}

#define LDSM4(r, addr) \
    asm volatile("ldmatrix.sync.aligned.m8n8.x4.shared.b16 {%0,%1,%2,%3}, [%4];" \
                 : "=r"((r)[0]), "=r"((r)[1]), "=r"((r)[2]), "=r"((r)[3])        \
                 : "r"(addr))

#define MMA16816(acc, A, Bp) \
    asm volatile("mma.sync.aligned.m16n8k16.row.col.f32.bf16.bf16.f32 "          \
                 "{%0,%1,%2,%3}, {%4,%5,%6,%7}, {%8,%9}, {%0,%1,%2,%3};"         \
                 : "+f"((acc)[0]), "+f"((acc)[1]), "+f"((acc)[2]), "+f"((acc)[3])\
                 : "r"((A)[0]), "r"((A)[1]), "r"((A)[2]), "r"((A)[3]),           \
                   "r"((Bp)[0]), "r"((Bp)[1]))

// Split float4 into 3 bf16 planes, packed as 2 x u32 (4 bf16 = 8B) per plane.
__device__ __forceinline__ void cvt4(float4 v, uint32_t out[3][2]) {
    float x[4] = {v.x, v.y, v.z, v.w};
    uint32_t h[4], m[4], l[4];
#pragma unroll
    for (int j = 0; j < 4; j++) {
        __nv_bfloat16 bh = __float2bfloat16_rn(x[j]);
        float r1 = x[j] - __bfloat162float(bh);
        __nv_bfloat16 bm = __float2bfloat16_rn(r1);
        float r2 = r1 - __bfloat162float(bm);
        __nv_bfloat16 bl = __float2bfloat16_rn(r2);
        h[j] = (uint32_t)__bfloat16_as_ushort(bh);
        m[j] = (uint32_t)__bfloat16_as_ushort(bm);
        l[j] = (uint32_t)__bfloat16_as_ushort(bl);
    }
    out[0][0] = h[0] | (h[1] << 16);  out[0][1] = h[2] | (h[3] << 16);
    out[1][0] = m[0] | (m[1] << 16);  out[1][1] = m[2] | (m[3] << 16);
    out[2][0] = l[0] | (l[1] << 16);  out[2][1] = l[2] | (l[3] << 16);
}

__global__ __launch_bounds__(256, 1) void gemm_kernel(
    const float* __restrict__ H, const float* __restrict__ Wm)
{
    extern __shared__ __align__(16) char smem[];
    const uint32_t sbase = smem_to_u32(smem);
    const int tid  = threadIdx.x;
    const int warp = tid >> 5;
    const int lane = tid & 31;
    const int mtile = blockIdx.x >> 1;
    const int split = blockIdx.x & 1;
    const int row0  = mtile * 128;
    const int kb0   = split * KRANGE;

    float accM[8][4], accC[8][4];
#pragma unroll
    for (int n = 0; n < 8; n++)
#pragma unroll
        for (int j = 0; j < 4; j++) { accM[n][j] = 0.f; accC[n][j] = 0.f; }

    // ldmatrix per-lane base addresses (fixed; +plane, +kstep*32 at use).
    // A x4: lanes 0-15 -> rows 0-15 (k+0), lanes 16-31 -> rows 0-15 (k+8).
    const uint32_t aBase = sbase
        + (uint32_t)((warp * 16 + (lane & 15)) * PITCH + ((lane >> 4) << 4));
    // B x4: m0=n0-7,k0; m1=n0-7,k8; m2=n8-15,k0; m3=n8-15,k8.
    const uint32_t bBase = sbase + SB_OFF
        + (uint32_t)((((lane & 7) | ((lane >> 4) << 3)) * PITCH) + (((lane >> 3) & 1) << 4));

    // Load/store geometry: q = tid + 256*i -> row = q>>4, seg = tid&15 (16B units).
    const int seg   = tid & 15;
    const int rA    = tid >> 4;          // + 16*i
    const uint32_t stsOff = (uint32_t)(seg * 8);   // bf16-plane byte offset in row

    float4 pa[8], pb[4];
#pragma unroll
    for (int i = 0; i < 8; i++)
        pa[i] = *(const float4*)(H + (size_t)(row0 + rA + 16 * i) * D_DIM + kb0 + seg * 4);
#pragma unroll
    for (int j = 0; j < 4; j++)
        pb[j] = *(const float4*)(Wm + (size_t)(rA + 16 * j) * D_DIM + kb0 + seg * 4);

    for (int c = 0; c < NCHUNK; c++) {
        __syncthreads();   // previous chunk's readers are done
        // Convert & store chunk c into the 3 bf16 planes.
#pragma unroll
        for (int i = 0; i < 8; i++) {
            uint32_t o[3][2];
            cvt4(pa[i], o);
            const uint32_t ro = (uint32_t)((rA + 16 * i) * PITCH) + stsOff;
#pragma unroll
            for (int p = 0; p < 3; p++)
                *(uint2*)(smem + p * A_PLANE + ro) = make_uint2(o[p][0], o[p][1]);
        }
#pragma unroll
        for (int j = 0; j < 4; j++) {
            uint32_t o[3][2];
            cvt4(pb[j], o);
            const uint32_t ro = (uint32_t)((rA + 16 * j) * PITCH) + stsOff;
#pragma unroll
            for (int p = 0; p < 3; p++)
                *(uint2*)(smem + SB_OFF + p * B_PLANE + ro) = make_uint2(o[p][0], o[p][1]);
        }
        __syncthreads();

        if (c + 1 < NCHUNK) {   // prefetch next chunk (overlaps mma phase)
            const int kb = kb0 + (c + 1) * BKC;
#pragma unroll
            for (int i = 0; i < 8; i++)
                pa[i] = *(const float4*)(H + (size_t)(row0 + rA + 16 * i) * D_DIM + kb + seg * 4);
#pragma unroll
            for (int j = 0; j < 4; j++)
                pb[j] = *(const float4*)(Wm + (size_t)(rA + 16 * j) * D_DIM + kb + seg * 4);
        }

#pragma unroll
        for (int s = 0; s < 4; s++) {
            const uint32_t ks = (uint32_t)(s * 32);
            uint32_t Ah[4], Am[4], Al[4];
            LDSM4(Ah, aBase + 0 * A_PLANE + ks);
            LDSM4(Am, aBase + 1 * A_PLANE + ks);
            LDSM4(Al, aBase + 2 * A_PLANE + ks);
            uint32_t Bh[16], Bm[16], Bl[16];   // [n-tile*2 + {0,1}]
#pragma unroll
            for (int np = 0; np < 4; np++) {
                const uint32_t bo = bBase + (uint32_t)(np * 16 * PITCH) + ks;
                LDSM4(&Bh[np * 4], bo + 0 * B_PLANE);
                LDSM4(&Bm[np * 4], bo + 1 * B_PLANE);
                LDSM4(&Bl[np * 4], bo + 2 * B_PLANE);
            }
            // Term-major sweeps: each acc touched once per 8 mmas (no RAW stalls).
#pragma unroll
            for (int n = 0; n < 8; n++) MMA16816(accM[n], Ah, &Bh[n * 2]);
#pragma unroll
            for (int n = 0; n < 8; n++) MMA16816(accC[n], Ah, &Bm[n * 2]);
#pragma unroll
            for (int n = 0; n < 8; n++) MMA16816(accC[n], Am, &Bh[n * 2]);
#pragma unroll
            for (int n = 0; n < 8; n++) MMA16816(accC[n], Am, &Bm[n * 2]);
#pragma unroll
            for (int n = 0; n < 8; n++) MMA16816(accC[n], Ah, &Bl[n * 2]);
#pragma unroll
            for (int n = 0; n < 8; n++) MMA16816(accC[n], Al, &Bh[n * 2]);
        }
    }

    // Write partials. C-frag: reg j -> (row g(+8), col 2t(+1)), g=lane>>2, t=lane&3.
    const int g  = lane >> 2;
    const int t2 = (lane & 3) * 2;
    const int rowA = row0 + warp * 16 + g;
#pragma unroll
    for (int n = 0; n < 8; n++) {
        float v0 = accM[n][0] + accC[n][0];
        float v1 = accM[n][1] + accC[n][1];
        float v2 = accM[n][2] + accC[n][2];
        float v3 = accM[n][3] + accC[n][3];
        *(float2*)&g_partial[split][(size_t)rowA * E_DIM + n * 8 + t2]       = make_float2(v0, v1);
        *(float2*)&g_partial[split][(size_t)(rowA + 8) * E_DIM + n * 8 + t2] = make_float2(v2, v3);
    }
}

// ===========================================================================
// Epilogue: logits = partial0 + partial1 + bias; JAX partitionable threefry
// Gumbel (bits = x0^x1), softmax(clean logits), rank-based top-k mask.
// ===========================================================================

__device__ __forceinline__ uint32_t rotl32(uint32_t x, int r) {
    return (x << r) | (x >> (32 - r));
}
__device__ __forceinline__ uint32_t threefry_xor_42(uint32_t c1) {
    const uint32_t ks0 = 0u, ks1 = 42u;
    const uint32_t ks2 = 0x1BD11BDAu ^ ks0 ^ ks1;
    uint32_t x0 = 0u + ks0, x1 = c1 + ks1;
#define TF_R(r) { x0 += x1; x1 = rotl32(x1, (r)); x1 ^= x0; }
    TF_R(13) TF_R(15) TF_R(26) TF_R(6)   x0 += ks1; x1 += ks2 + 1u;
    TF_R(17) TF_R(29) TF_R(16) TF_R(24)  x0 += ks2; x1 += ks0 + 2u;
    TF_R(13) TF_R(15) TF_R(26) TF_R(6)   x0 += ks0; x1 += ks1 + 3u;
    TF_R(17) TF_R(29) TF_R(16) TF_R(24)  x0 += ks1; x1 += ks2 + 4u;
    TF_R(13) TF_R(15) TF_R(26) TF_R(6)   x0 += ks2; x1 += ks0 + 5u;
#undef TF_R
    return x0 ^ x1;
}
__device__ __forceinline__ float gumbel_from_bits(uint32_t bits) {
    float f = __uint_as_float((bits >> 9) | 0x3F800000u) - 1.0f;
    const float lo = 1e-6f;
    const float hi = (float)(1.0 - 1e-6);
    float u = fmaxf(lo, __fadd_rn(__fmul_rn(f, __fsub_rn(hi, lo)), lo));
    return -logf(-logf(u));
}

__global__ __launch_bounds__(256) void epilogue_kernel(
    const float* __restrict__ bias, const int* __restrict__ kptr,
    float* __restrict__ mask_out, float* __restrict__ wout,
    float* __restrict__ logits_out)
{
    __shared__ float ss[8][64];
    const int w    = threadIdx.x >> 5;
    const int lane = threadIdx.x & 31;
    const int row  = blockIdx.x * 8 + w;
    const int k    = *kptr;
    const int e0 = lane, e1 = lane + 32;
    const size_t base = (size_t)row * E_DIM;

    float l0 = (g_partial[0][base + e0] + g_partial[1][base + e0]) + bias[e0];
    float l1 = (g_partial[0][base + e1] + g_partial[1][base + e1]) + bias[e1];
    logits_out[base + e0] = l0;
    logits_out[base + e1] = l1;

    uint32_t i0 = (uint32_t)(row * E_DIM + e0);
    float s0 = l0 + gumbel_from_bits(threefry_xor_42(i0));
    float s1 = l1 + gumbel_from_bits(threefry_xor_42(i0 + 32u));

    float m = fmaxf(l0, l1);
#pragma unroll
    for (int off = 16; off; off >>= 1)
        m = fmaxf(m, __shfl_xor_sync(0xffffffffu, m, off));
    float p0 = expf(l0 - m), p1 = expf(l1 - m);
    float sum = p0 + p1;
#pragma unroll
    for (int off = 16; off; off >>= 1)
        sum += __shfl_xor_sync(0xffffffffu, sum, off);

    ss[w][e0] = s0;
    ss[w][e1] = s1;
    __syncwarp();
    int c0 = 0, c1 = 0;
#pragma unroll
    for (int jj = 0; jj < 64; jj++) {
        float v = ss[w][jj];
        c0 += (v > s0) || ((v == s0) && (jj < e0));
        c1 += (v > s1) || ((v == s1) && (jj < e1));
    }

    mask_out[base + e0] = (c0 < k) ? 1.0f : 0.0f;
    mask_out[base + e1] = (c1 < k) ? 1.0f : 0.0f;
    wout[base + e0] = p0 / sum;
    wout[base + e1] = p1 / sum;
}

// ===========================================================================
// Launch. Inputs matched by element count (h=33.5M, W=262144, bias=64, k=1).
// out = [mask | weight | logits], each T*E float32.
// ===========================================================================
extern "C" void kernel_launch(void* const* d_in, const int* in_sizes, int n_in,
                              void* d_out, int out_size) {
    const float* H    = nullptr;
    const float* Wm   = nullptr;
    const float* bias = nullptr;
    const int*   kptr = nullptr;
    for (int i = 0; i < n_in; i++) {
        long long sz = in_sizes[i];
        if (sz == (long long)T_DIM * D_DIM)      H    = (const float*)d_in[i];
        else if (sz == (long long)E_DIM * D_DIM) Wm   = (const float*)d_in[i];
        else if (sz == E_DIM)                    bias = (const float*)d_in[i];
        else if (sz == 1)                        kptr = (const int*)d_in[i];
    }
    if (!H)    H    = (const float*)d_in[0];
    if (!Wm)   Wm   = (const float*)d_in[1];
    if (!bias) bias = (const float*)d_in[2];
    if (!kptr) kptr = (const int*)d_in[3];

    float* out        = (float*)d_out;
    float* mask_out   = out;
    float* weight_out = out + (size_t)T_DIM * E_DIM;
    float* logits_out = out + 2 * (size_t)T_DIM * E_DIM;

    cudaFuncSetAttribute(gemm_kernel,
                         cudaFuncAttributeMaxDynamicSharedMemorySize, SMEM_BYTES);
    gemm_kernel<<<(T_DIM / 128) * KSPLIT, 256, SMEM_BYTES>>>(H, Wm);
    epilogue_kernel<<<T_DIM / 8, 256>>>(bias, kptr, mask_out, weight_out, logits_out);
}

// round 9
// speedup vs baseline: 4.2915x; 1.7798x over previous
#include <cuda_runtime.h>
#include <cuda_fp16.h>
#include <cstdint>

#define T_DIM 8192
#define D_DIM 4096
#define E_DIM 64

// ===========================================================================
// GEMM via legacy mma.sync m16n8k16 fp16 (base PTX -> compiles for sm_103).
// Scaled fp16x2 split: hi = f16(x), lo = f16((x - hi) * 2048)  [lo stays in
// fp16 normal range -> no subnormal truncation]. Keep hi*hi (accM) and
// hi*lo + lo*hi (accC); result = accM + accC/2048. Logit rms err ~3e-7.
// Grid: 64 M-tiles (128 rows) x K-split 2 = 128 CTAs, 256 threads.
// Double-buffered smem (2 x 54 KB): STS(c+1) overlaps MMA(c), 1 sync/chunk.
// ===========================================================================

constexpr int KSPLIT  = 2;
constexpr int KRANGE  = D_DIM / KSPLIT;   // 2048
constexpr int BKC     = 64;               // K per chunk
constexpr int NCHUNK  = KRANGE / BKC;     // 32
constexpr int PITCH   = 144;              // bytes per f16 row (128 data + 16 pad)
constexpr int A_PLANE = 128 * PITCH;      // 18432
constexpr int B_PLANE = 64 * PITCH;       // 9216
constexpr int SB_OFF  = 2 * A_PLANE;
constexpr int BUF     = 2 * A_PLANE + 2 * B_PLANE;   // 55296
constexpr int SMEM_BYTES = 2 * BUF;                   // 110592
constexpr float LO_SCALE   = 2048.0f;
constexpr float LO_UNSCALE = 1.0f / 2048.0f;

__device__ float g_partial[KSPLIT][(size_t)T_DIM * E_DIM];   // 4 MB scratch

__device__ __forceinline__ uint32_t smem_to_u32(const void* p) {
    uint32_t a;
    asm("{ .reg .u64 t; cvta.to.shared.u64 t, %1; cvt.u32.u64 %0, t; }"
        : "=r"(a) : "l"(p));
    return a;
}

#define LDSM4(r, addr) \
    asm volatile("ldmatrix.sync.aligned.m8n8.x4.shared.b16 {%0,%1,%2,%3}, [%4];" \
                 : "=r"((r)[0]), "=r"((r)[1]), "=r"((r)[2]), "=r"((r)[3])        \
                 : "r"(addr))

#define MMA16816(acc, A, Bp) \
    asm volatile("mma.sync.aligned.m16n8k16.row.col.f32.f16.f16.f32 "            \
                 "{%0,%1,%2,%3}, {%4,%5,%6,%7}, {%8,%9}, {%0,%1,%2,%3};"         \
                 : "+f"((acc)[0]), "+f"((acc)[1]), "+f"((acc)[2]), "+f"((acc)[3])\
                 : "r"((A)[0]), "r"((A)[1]), "r"((A)[2]), "r"((A)[3]),           \
                   "r"((Bp)[0]), "r"((Bp)[1]))

// Split float4 into hi and scaled-lo fp16 planes.
__device__ __forceinline__ void cvt4h(float4 v, uint2& hi, uint2& lo) {
    __half2 h0 = __floats2half2_rn(v.x, v.y);
    __half2 h1 = __floats2half2_rn(v.z, v.w);
    float2 f0 = __half22float2(h0), f1 = __half22float2(h1);
    __half2 l0 = __floats2half2_rn((v.x - f0.x) * LO_SCALE, (v.y - f0.y) * LO_SCALE);
    __half2 l1 = __floats2half2_rn((v.z - f1.x) * LO_SCALE, (v.w - f1.y) * LO_SCALE);
    hi = make_uint2(*reinterpret_cast<uint32_t*>(&h0), *reinterpret_cast<uint32_t*>(&h1));
    lo = make_uint2(*reinterpret_cast<uint32_t*>(&l0), *reinterpret_cast<uint32_t*>(&l1));
}

__global__ __launch_bounds__(256, 1) void gemm_kernel(
    const float* __restrict__ H, const float* __restrict__ Wm)
{
    extern __shared__ __align__(16) char smem[];
    const uint32_t sbase = smem_to_u32(smem);
    const int tid  = threadIdx.x;
    const int warp = tid >> 5;
    const int lane = tid & 31;
    const int mtile = blockIdx.x >> 1;
    const int split = blockIdx.x & 1;
    const int row0  = mtile * 128;
    const int kb0   = split * KRANGE;

    float accM[8][4], accC[8][4];
#pragma unroll
    for (int n = 0; n < 8; n++)
#pragma unroll
        for (int j = 0; j < 4; j++) { accM[n][j] = 0.f; accC[n][j] = 0.f; }

    // ldmatrix per-lane base addresses (buffer 0; add (c&1)*BUF at use).
    const uint32_t aBase = sbase
        + (uint32_t)((warp * 16 + (lane & 15)) * PITCH + ((lane >> 4) << 4));
    const uint32_t bBase = sbase + SB_OFF
        + (uint32_t)((((lane & 7) | ((lane >> 4) << 3)) * PITCH) + (((lane >> 3) & 1) << 4));

    // Load/store geometry: q = tid + 256*i -> row = q>>4, seg = tid&15.
    const int seg = tid & 15;
    const int rA  = tid >> 4;                       // + 16*i
    const uint32_t stsOff = (uint32_t)(seg * 8);    // 4 halves = 8 B

    float4 pa[8], pb[4];
#pragma unroll
    for (int i = 0; i < 8; i++)
        pa[i] = *(const float4*)(H + (size_t)(row0 + rA + 16 * i) * D_DIM + kb0 + seg * 4);
#pragma unroll
    for (int j = 0; j < 4; j++)
        pb[j] = *(const float4*)(Wm + (size_t)(rA + 16 * j) * D_DIM + kb0 + seg * 4);

    // Prologue: fill buffer 0 with chunk 0.
#pragma unroll
    for (int i = 0; i < 8; i++) {
        uint2 h, l;
        cvt4h(pa[i], h, l);
        const uint32_t ro = (uint32_t)((rA + 16 * i) * PITCH) + stsOff;
        *(uint2*)(smem + 0 * A_PLANE + ro) = h;
        *(uint2*)(smem + 1 * A_PLANE + ro) = l;
    }
#pragma unroll
    for (int j = 0; j < 4; j++) {
        uint2 h, l;
        cvt4h(pb[j], h, l);
        const uint32_t ro = (uint32_t)((rA + 16 * j) * PITCH) + stsOff;
        *(uint2*)(smem + SB_OFF + 0 * B_PLANE + ro) = h;
        *(uint2*)(smem + SB_OFF + 1 * B_PLANE + ro) = l;
    }
    __syncthreads();

    for (int c = 0; c < NCHUNK; c++) {
        const uint32_t bufR = (uint32_t)((c & 1) * BUF);
        const uint32_t bufW = (uint32_t)(((c + 1) & 1) * BUF);

        if (c + 1 < NCHUNK) {   // issue LDG early; consumed after the MMA sweep
            const int kb = kb0 + (c + 1) * BKC;
#pragma unroll
            for (int i = 0; i < 8; i++)
                pa[i] = *(const float4*)(H + (size_t)(row0 + rA + 16 * i) * D_DIM + kb + seg * 4);
#pragma unroll
            for (int j = 0; j < 4; j++)
                pb[j] = *(const float4*)(Wm + (size_t)(rA + 16 * j) * D_DIM + kb + seg * 4);
        }

#pragma unroll
        for (int s = 0; s < 4; s++) {
            const uint32_t ks = (uint32_t)(s * 32);
            uint32_t Ah[4], Al[4];
            LDSM4(Ah, aBase + bufR + 0 * A_PLANE + ks);
            LDSM4(Al, aBase + bufR + 1 * A_PLANE + ks);
            uint32_t Bh[16], Bl[16];
#pragma unroll
            for (int np = 0; np < 4; np++) {
                const uint32_t bo = bBase + bufR + (uint32_t)(np * 16 * PITCH) + ks;
                LDSM4(&Bh[np * 4], bo + 0 * B_PLANE);
                LDSM4(&Bl[np * 4], bo + 1 * B_PLANE);
            }
            // Term-major sweeps; each acc touched every 8 MMAs (no RAW stalls).
#pragma unroll
            for (int n = 0; n < 8; n++) MMA16816(accM[n], Ah, &Bh[n * 2]);
#pragma unroll
            for (int n = 0; n < 8; n++) MMA16816(accC[n], Ah, &Bl[n * 2]);
#pragma unroll
            for (int n = 0; n < 8; n++) MMA16816(accC[n], Al, &Bh[n * 2]);
        }

        if (c + 1 < NCHUNK) {   // convert + STS into the other buffer
#pragma unroll
            for (int i = 0; i < 8; i++) {
                uint2 h, l;
                cvt4h(pa[i], h, l);
                const uint32_t ro = (uint32_t)((rA + 16 * i) * PITCH) + stsOff;
                *(uint2*)(smem + bufW + 0 * A_PLANE + ro) = h;
                *(uint2*)(smem + bufW + 1 * A_PLANE + ro) = l;
            }
#pragma unroll
            for (int j = 0; j < 4; j++) {
                uint2 h, l;
                cvt4h(pb[j], h, l);
                const uint32_t ro = (uint32_t)((rA + 16 * j) * PITCH) + stsOff;
                *(uint2*)(smem + bufW + SB_OFF + 0 * B_PLANE + ro) = h;
                *(uint2*)(smem + bufW + SB_OFF + 1 * B_PLANE + ro) = l;
            }
        }
        __syncthreads();
    }

    // Write partials: value = accM + accC/2048. C-frag: reg j -> (row g(+8), col 2t(+1)).
    const int g  = lane >> 2;
    const int t2 = (lane & 3) * 2;
    const int rowA = row0 + warp * 16 + g;
#pragma unroll
    for (int n = 0; n < 8; n++) {
        float v0 = fmaf(accC[n][0], LO_UNSCALE, accM[n][0]);
        float v1 = fmaf(accC[n][1], LO_UNSCALE, accM[n][1]);
        float v2 = fmaf(accC[n][2], LO_UNSCALE, accM[n][2]);
        float v3 = fmaf(accC[n][3], LO_UNSCALE, accM[n][3]);
        *(float2*)&g_partial[split][(size_t)rowA * E_DIM + n * 8 + t2]       = make_float2(v0, v1);
        *(float2*)&g_partial[split][(size_t)(rowA + 8) * E_DIM + n * 8 + t2] = make_float2(v2, v3);
    }
}

// ===========================================================================
// Epilogue: logits = partial0 + partial1 + bias; JAX partitionable threefry
// Gumbel (bits = x0^x1), softmax(clean logits), rank-based top-k mask.
// ===========================================================================

__device__ __forceinline__ uint32_t rotl32(uint32_t x, int r) {
    return (x << r) | (x >> (32 - r));
}
__device__ __forceinline__ uint32_t threefry_xor_42(uint32_t c1) {
    const uint32_t ks0 = 0u, ks1 = 42u;
    const uint32_t ks2 = 0x1BD11BDAu ^ ks0 ^ ks1;
    uint32_t x0 = 0u + ks0, x1 = c1 + ks1;
#define TF_R(r) { x0 += x1; x1 = rotl32(x1, (r)); x1 ^= x0; }
    TF_R(13) TF_R(15) TF_R(26) TF_R(6)   x0 += ks1; x1 += ks2 + 1u;
    TF_R(17) TF_R(29) TF_R(16) TF_R(24)  x0 += ks2; x1 += ks0 + 2u;
    TF_R(13) TF_R(15) TF_R(26) TF_R(6)   x0 += ks0; x1 += ks1 + 3u;
    TF_R(17) TF_R(29) TF_R(16) TF_R(24)  x0 += ks1; x1 += ks2 + 4u;
    TF_R(13) TF_R(15) TF_R(26) TF_R(6)   x0 += ks2; x1 += ks0 + 5u;
#undef TF_R
    return x0 ^ x1;
}
__device__ __forceinline__ float gumbel_from_bits(uint32_t bits) {
    float f = __uint_as_float((bits >> 9) | 0x3F800000u) - 1.0f;
    const float lo = 1e-6f;
    const float hi = (float)(1.0 - 1e-6);
    float u = fmaxf(lo, __fadd_rn(__fmul_rn(f, __fsub_rn(hi, lo)), lo));
    return -logf(-logf(u));
}

__global__ __launch_bounds__(256) void epilogue_kernel(
    const float* __restrict__ bias, const int* __restrict__ kptr,
    float* __restrict__ mask_out, float* __restrict__ wout,
    float* __restrict__ logits_out)
{
    __shared__ float ss[8][64];
    const int w    = threadIdx.x >> 5;
    const int lane = threadIdx.x & 31;
    const int row  = blockIdx.x * 8 + w;
    const int k    = *kptr;
    const int e0 = lane, e1 = lane + 32;
    const size_t base = (size_t)row * E_DIM;

    float l0 = (g_partial[0][base + e0] + g_partial[1][base + e0]) + bias[e0];
    float l1 = (g_partial[0][base + e1] + g_partial[1][base + e1]) + bias[e1];
    logits_out[base + e0] = l0;
    logits_out[base + e1] = l1;

    uint32_t i0 = (uint32_t)(row * E_DIM + e0);
    float s0 = l0 + gumbel_from_bits(threefry_xor_42(i0));
    float s1 = l1 + gumbel_from_bits(threefry_xor_42(i0 + 32u));

    float m = fmaxf(l0, l1);
#pragma unroll
    for (int off = 16; off; off >>= 1)
        m = fmaxf(m, __shfl_xor_sync(0xffffffffu, m, off));
    float p0 = expf(l0 - m), p1 = expf(l1 - m);
    float sum = p0 + p1;
#pragma unroll
    for (int off = 16; off; off >>= 1)
        sum += __shfl_xor_sync(0xffffffffu, sum, off);

    ss[w][e0] = s0;
    ss[w][e1] = s1;
    __syncwarp();
    int c0 = 0, c1 = 0;
#pragma unroll
    for (int jj = 0; jj < 64; jj++) {
        float v = ss[w][jj];
        c0 += (v > s0) || ((v == s0) && (jj < e0));
        c1 += (v > s1) || ((v == s1) && (jj < e1));
    }

    mask_out[base + e0] = (c0 < k) ? 1.0f : 0.0f;
    mask_out[base + e1] = (c1 < k) ? 1.0f : 0.0f;
    wout[base + e0] = p0 / sum;
    wout[base + e1] = p1 / sum;
}

// ===========================================================================
// Launch. Inputs matched by element count (h=33.5M, W=262144, bias=64, k=1).
// out = [mask | weight | logits], each T*E float32.
// ===========================================================================
extern "C" void kernel_launch(void* const* d_in, const int* in_sizes, int n_in,
                              void* d_out, int out_size) {
    const float* H    = nullptr;
    const float* Wm   = nullptr;
    const float* bias = nullptr;
    const int*   kptr = nullptr;
    for (int i = 0; i < n_in; i++) {
        long long sz = in_sizes[i];
        if (sz == (long long)T_DIM * D_DIM)      H    = (const float*)d_in[i];
        else if (sz == (long long)E_DIM * D_DIM) Wm   = (const float*)d_in[i];
        else if (sz == E_DIM)                    bias = (const float*)d_in[i];
        else if (sz == 1)                        kptr = (const int*)d_in[i];
    }
    if (!H)    H    = (const float*)d_in[0];
    if (!Wm)   Wm   = (const float*)d_in[1];
    if (!bias) bias = (const float*)d_in[2];
    if (!kptr) kptr = (const int*)d_in[3];

    float* out        = (float*)d_out;
    float* mask_out   = out;
    float* weight_out = out + (size_t)T_DIM * E_DIM;
    float* logits_out = out + 2 * (size_t)T_DIM * E_DIM;

    cudaFuncSetAttribute(gemm_kernel,
                         cudaFuncAttributeMaxDynamicSharedMemorySize, SMEM_BYTES);
    gemm_kernel<<<(T_DIM / 128) * KSPLIT, 256, SMEM_BYTES>>>(H, Wm);
    epilogue_kernel<<<T_DIM / 8, 256>>>(bias, kptr, mask_out, weight_out, logits_out);
}